// round 1
// baseline (speedup 1.0000x reference)
#include <cuda_runtime.h>
#include <math.h>

#define Bn 4
#define Sn 4096
#define Cn 256
#define En 256

typedef unsigned long long u64;

// Scratch for projected Q, K, V (static device arrays: no allocation).
__device__ float g_Q[Bn * Sn * Cn];
__device__ float g_K[Bn * Sn * Cn];
__device__ float g_V[Bn * Sn * En];

// ---- packed f32x2 helpers (FFMA2 path, sm_100+) ----
__device__ __forceinline__ u64 pk2(float lo, float hi) {
    u64 r; asm("mov.b64 %0, {%1,%2};" : "=l"(r) : "f"(lo), "f"(hi)); return r;
}
__device__ __forceinline__ void fma2(u64& d, u64 a, u64 b) {
    asm("fma.rn.f32x2 %0, %1, %2, %0;" : "+l"(d) : "l"(a), "l"(b));
}
__device__ __forceinline__ void mul2(u64& d, u64 a) {
    asm("mul.rn.f32x2 %0, %0, %1;" : "+l"(d) : "l"(a));
}
__device__ __forceinline__ void upk2(u64 v, float& lo, float& hi) {
    asm("mov.b64 {%0,%1}, %2;" : "=f"(lo), "=f"(hi) : "l"(v));
}

// ============================================================
// Kernel 1: QKV projections.
// out[m][n] = sum_k x[m][k] * W[k][n] + b[n]
// M=16384, K=256. grid.y selects (which matrix, 64-col block).
// Tile 128x64, 256 threads, thread tile 8x4 (f32x2 packed over n).
// ============================================================
__global__ __launch_bounds__(256)
void qkv_proj_kernel(const float* __restrict__ x,
                     const float* __restrict__ Wq, const float* __restrict__ bq,
                     const float* __restrict__ Wk, const float* __restrict__ bk,
                     const float* __restrict__ Wv, const float* __restrict__ bv)
{
    __shared__ float Xs[16][132];   // transposed x chunk: [k][m], padded
    __shared__ float Wsh[16][64];   // W chunk: [k][n]

    int t  = threadIdx.x;
    int m0 = blockIdx.x * 128;
    int nb = blockIdx.y;            // 0..11
    int which = nb >> 2;
    int n0 = (nb & 3) * 64;

    const float* W; const float* bias; float* og;
    if (which == 0)      { W = Wq; bias = bq; og = g_Q; }
    else if (which == 1) { W = Wk; bias = bk; og = g_K; }
    else                 { W = Wv; bias = bv; og = g_V; }

    int tr = t >> 4, tc = t & 15;   // 16x16 thread grid

    u64 acc[8][2];
    #pragma unroll
    for (int i = 0; i < 8; i++) { acc[i][0] = 0ull; acc[i][1] = 0ull; }

    for (int kc = 0; kc < Cn; kc += 16) {
        __syncthreads();
        // load x tile 128x16 (transposed into Xs[k][m])
        for (int i = t; i < 512; i += 256) {
            int row = i >> 2, seg = i & 3;
            float4 v = *(const float4*)&x[(size_t)(m0 + row) * Cn + kc + seg * 4];
            Xs[seg*4+0][row] = v.x; Xs[seg*4+1][row] = v.y;
            Xs[seg*4+2][row] = v.z; Xs[seg*4+3][row] = v.w;
        }
        // load W tile 16x64
        {
            int row = t >> 4, seg = t & 15;
            *(float4*)&Wsh[row][seg*4] =
                *(const float4*)&W[(size_t)(kc + row) * 256 + n0 + seg * 4];
        }
        __syncthreads();

        #pragma unroll
        for (int k = 0; k < 16; ++k) {
            float4 a0 = *(float4*)&Xs[k][tr*8];
            float4 a1 = *(float4*)&Xs[k][tr*8 + 4];
            float4 bb = *(float4*)&Wsh[k][tc*4];
            u64 b01 = pk2(bb.x, bb.y), b23 = pk2(bb.z, bb.w);
            float av[8] = {a0.x,a0.y,a0.z,a0.w,a1.x,a1.y,a1.z,a1.w};
            #pragma unroll
            for (int i = 0; i < 8; ++i) {
                u64 ad = pk2(av[i], av[i]);
                fma2(acc[i][0], ad, b01);
                fma2(acc[i][1], ad, b23);
            }
        }
    }

    float4 bb4 = *(const float4*)&bias[n0 + tc*4];
    #pragma unroll
    for (int i = 0; i < 8; ++i) {
        float x0, x1, x2, x3;
        upk2(acc[i][0], x0, x1);
        upk2(acc[i][1], x2, x3);
        float4 r;
        r.x = x0 + bb4.x; r.y = x1 + bb4.y; r.z = x2 + bb4.z; r.w = x3 + bb4.w;
        *(float4*)&og[(size_t)(m0 + tr*8 + i) * 256 + n0 + tc*4] = r;
    }
}

// ============================================================
// Kernel 2: flash attention + sigmoid.
// One block per (batch, 64-query tile). 256 threads.
// Key tiles of 64, online softmax, all fp32 with f32x2 FMAs.
// K is stored c-major in smem ([c][j]) with an XOR group swizzle
// so score-phase float4 loads are bank-conflict-free.
// ============================================================
#define ATTN_SMEM_FLOATS (64*256 + 256*68 + 64*256 + 64*68 + 192)
#define ATTN_SMEM_BYTES  (ATTN_SMEM_FLOATS * 4)

__global__ __launch_bounds__(256, 1)
void attn_kernel(float* __restrict__ out)
{
    extern __shared__ float sm[];
    float* Qs    = sm;                  // [64][256]
    float* Kst   = Qs  + 64*256;        // [256][68]  c-major, swizzled groups
    float* Vs    = Kst + 256*68;        // [64][256]
    float* Ps    = Vs  + 64*256;        // [64][68]
    float* row_m = Ps  + 64*68;         // [64]
    float* row_l = row_m + 64;          // [64]
    float* row_s = row_l + 64;          // [64] per-tile rescale

    int t  = threadIdx.x;
    int b  = blockIdx.y, qt = blockIdx.x;

    const float* Qg = g_Q + ((size_t)b * Sn + qt * 64) * Cn;
    const float* Kg = g_K + (size_t)b * Sn * Cn;
    const float* Vg = g_V + (size_t)b * Sn * En;

    // load Q tile (64 x 256)
    for (int i = t; i < 64*64; i += 256) {
        int r = i >> 6, seg = i & 63;
        *(float4*)&Qs[r*256 + seg*4] = *(const float4*)&Qg[r*Cn + seg*4];
    }
    if (t < 64) { row_m[t] = -INFINITY; row_l[t] = 0.f; }

    int tr = t >> 4, tc = t & 15;
    int r0 = tr * 4;                    // this thread's 4 query rows

    u64 o2[4][8];                       // O accum: 4 rows x 16 e-cols (8 f32x2)
    #pragma unroll
    for (int i = 0; i < 4; i++)
        #pragma unroll
        for (int q = 0; q < 8; q++) o2[i][q] = 0ull;

    for (int kt = 0; kt < 64; ++kt) {
        __syncthreads();                // prev PV done / Qs+stats ready
        const float* Kt = Kg + (size_t)kt * 64 * Cn;
        const float* Vt = Vg + (size_t)kt * 64 * En;

        // ---- load K tile transposed into Kst[c][j], group-swizzled ----
        #pragma unroll
        for (int uu = 0; uu < 4; ++uu) {
            int u    = t + 256 * uu;
            int cblk = u & 63;          // 0..63  (c block of 4)
            int jblk = u >> 6;          // 0..15  (j block of 4)
            int c0   = cblk * 4;
            int j0u  = jblk * 4;
            float4 v0 = *(const float4*)&Kt[(j0u+0)*256 + c0];
            float4 v1 = *(const float4*)&Kt[(j0u+1)*256 + c0];
            float4 v2 = *(const float4*)&Kt[(j0u+2)*256 + c0];
            float4 v3 = *(const float4*)&Kt[(j0u+3)*256 + c0];
            int gp = (jblk ^ (cblk & 15)) * 4;    // swizzled physical group
            float4 s0; s0.x=v0.x; s0.y=v1.x; s0.z=v2.x; s0.w=v3.x;
            float4 s1; s1.x=v0.y; s1.y=v1.y; s1.z=v2.y; s1.w=v3.y;
            float4 s2w; s2w.x=v0.z; s2w.y=v1.z; s2w.z=v2.z; s2w.w=v3.z;
            float4 s3; s3.x=v0.w; s3.y=v1.w; s3.z=v2.w; s3.w=v3.w;
            *(float4*)&Kst[(c0+0)*68 + gp] = s0;
            *(float4*)&Kst[(c0+1)*68 + gp] = s1;
            *(float4*)&Kst[(c0+2)*68 + gp] = s2w;
            *(float4*)&Kst[(c0+3)*68 + gp] = s3;
        }
        // ---- load V tile (row-major) ----
        for (int i = t; i < 64*64; i += 256) {
            int r = i >> 6, seg = i & 63;
            *(float4*)&Vs[r*256 + seg*4] = *(const float4*)&Vt[r*256 + seg*4];
        }
        __syncthreads();

        // ---- scores: 4 rows x 4 cols per thread, dot over C=256 ----
        u64 s2[4][2];
        #pragma unroll
        for (int i = 0; i < 4; i++) { s2[i][0] = 0ull; s2[i][1] = 0ull; }

        #pragma unroll 2
        for (int c = 0; c < 256; c += 4) {
            int sw = (((c >> 2) & 15) ^ tc) * 4;
            const float* kbase = &Kst[c*68 + sw];
            float4 q[4];
            #pragma unroll
            for (int i = 0; i < 4; i++)
                q[i] = *(const float4*)&Qs[(r0+i)*256 + c];
            #pragma unroll
            for (int cc = 0; cc < 4; ++cc) {
                float4 k4 = *(const float4*)(kbase + cc*68);
                u64 k01 = pk2(k4.x, k4.y), k23 = pk2(k4.z, k4.w);
                #pragma unroll
                for (int i = 0; i < 4; i++) {
                    float qv = (cc == 0) ? q[i].x : (cc == 1) ? q[i].y
                             : (cc == 2) ? q[i].z : q[i].w;
                    u64 qd = pk2(qv, qv);
                    fma2(s2[i][0], qd, k01);
                    fma2(s2[i][1], qd, k23);
                }
            }
        }
        #pragma unroll
        for (int i = 0; i < 4; i++) {
            float a, bb, cc2, d;
            upk2(s2[i][0], a, bb); upk2(s2[i][1], cc2, d);
            float4 r; r.x = a; r.y = bb; r.z = cc2; r.w = d;
            *(float4*)&Ps[(r0+i)*68 + tc*4] = r;
        }
        __syncthreads();

        // ---- online softmax: warp w owns rows 8w..8w+7 ----
        {
            int w = t >> 5, lane = t & 31;
            #pragma unroll
            for (int rr = 0; rr < 8; ++rr) {
                int row = w * 8 + rr;
                float x0 = Ps[row*68 + lane];
                float x1 = Ps[row*68 + 32 + lane];
                float mx = fmaxf(x0, x1);
                #pragma unroll
                for (int off = 16; off > 0; off >>= 1)
                    mx = fmaxf(mx, __shfl_xor_sync(0xffffffffu, mx, off));
                float mold = row_m[row];
                float mnew = fmaxf(mold, mx);
                float p0 = __expf(x0 - mnew);
                float p1 = __expf(x1 - mnew);
                Ps[row*68 + lane]      = p0;
                Ps[row*68 + 32 + lane] = p1;
                float sum = p0 + p1;
                #pragma unroll
                for (int off = 16; off > 0; off >>= 1)
                    sum += __shfl_xor_sync(0xffffffffu, sum, off);
                if (lane == 0) {
                    float sc = __expf(mold - mnew);     // 0 on first tile
                    row_s[row] = sc;
                    row_l[row] = row_l[row] * sc + sum;
                    row_m[row] = mnew;
                }
            }
        }
        __syncthreads();

        // ---- rescale O, then accumulate P @ V ----
        #pragma unroll
        for (int i = 0; i < 4; i++) {
            float sc = row_s[r0 + i];
            u64 sd = pk2(sc, sc);
            #pragma unroll
            for (int q = 0; q < 8; q++) mul2(o2[i][q], sd);
        }
        #pragma unroll 4
        for (int j = 0; j < 64; ++j) {
            u64 pd[4];
            #pragma unroll
            for (int i = 0; i < 4; i++) {
                float p = Ps[(r0+i)*68 + j];
                pd[i] = pk2(p, p);
            }
            #pragma unroll
            for (int q = 0; q < 4; q++) {
                float4 vv = *(const float4*)&Vs[j*256 + q*64 + tc*4];
                u64 v01 = pk2(vv.x, vv.y), v23 = pk2(vv.z, vv.w);
                #pragma unroll
                for (int i = 0; i < 4; i++) {
                    fma2(o2[i][q*2],     v01, pd[i]);
                    fma2(o2[i][q*2 + 1], v23, pd[i]);
                }
            }
        }
    }

    // ---- epilogue: normalize, sigmoid, store ----
    float* Og = out + ((size_t)b * Sn + qt * 64) * En;
    #pragma unroll
    for (int i = 0; i < 4; i++) {
        float inv = 1.0f / row_l[r0 + i];
        #pragma unroll
        for (int q = 0; q < 4; q++) {
            float a, bb, cc2, d;
            upk2(o2[i][q*2],     a,   bb);
            upk2(o2[i][q*2 + 1], cc2, d);
            float4 r;
            r.x = 1.f / (1.f + __expf(-a   * inv));
            r.y = 1.f / (1.f + __expf(-bb  * inv));
            r.z = 1.f / (1.f + __expf(-cc2 * inv));
            r.w = 1.f / (1.f + __expf(-d   * inv));
            *(float4*)&Og[(size_t)(r0 + i) * En + q*64 + tc*4] = r;
        }
    }
}

// ============================================================
// Launch
// ============================================================
extern "C" void kernel_launch(void* const* d_in, const int* in_sizes, int n_in,
                              void* d_out, int out_size)
{
    const float* x  = (const float*)d_in[0];
    const float* Wq = (const float*)d_in[1];
    const float* bq = (const float*)d_in[2];
    const float* Wk = (const float*)d_in[3];
    const float* bk = (const float*)d_in[4];
    const float* Wv = (const float*)d_in[5];
    const float* bv = (const float*)d_in[6];
    float* out = (float*)d_out;

    // QKV projections: M blocks x (3 matrices * 4 col-blocks)
    qkv_proj_kernel<<<dim3(128, 12), 256>>>(x, Wq, bq, Wk, bk, Wv, bv);

    // Flash attention + sigmoid
    cudaFuncSetAttribute(attn_kernel, cudaFuncAttributeMaxDynamicSharedMemorySize,
                         ATTN_SMEM_BYTES);
    attn_kernel<<<dim3(64, 4), 256, ATTN_SMEM_BYTES>>>(out);
}

// round 3
// speedup vs baseline: 2.9302x; 2.9302x over previous
#include <cuda_runtime.h>
#include <cuda_bf16.h>
#include <math.h>
#include <stdint.h>

#define Bn 4
#define Sn 4096
#define Cn 256
#define En 256

typedef unsigned int u32;
typedef unsigned long long u64;

// ------------------------------------------------------------------
// Static device scratch (no allocation allowed)
// ------------------------------------------------------------------
__device__ float g_V[Bn * Sn * En];
__device__ __nv_bfloat16 g_Qh[Bn * Sn * Cn];
__device__ __nv_bfloat16 g_Ql[Bn * Sn * Cn];
__device__ __nv_bfloat16 g_Kh[Bn * Sn * Cn];
__device__ __nv_bfloat16 g_Kl[Bn * Sn * Cn];
__device__ __nv_bfloat16 g_Vth[Bn * En * Sn];   // V transposed: [b][e][s]
__device__ __nv_bfloat16 g_Vtl[Bn * En * Sn];
__device__ float g_S[(size_t)Bn * Sn * Sn];              // 256 MB
__device__ __nv_bfloat16 g_Ph[(size_t)Bn * Sn * Sn];     // 128 MB
__device__ __nv_bfloat16 g_Pl[(size_t)Bn * Sn * Sn];     // 128 MB

// ------------------------------------------------------------------
// helpers
// ------------------------------------------------------------------
__device__ __forceinline__ u32 smem_u32(const void* p) {
    u32 a;
    asm("{ .reg .u64 t; cvta.to.shared.u64 t, %1; cvt.u32.u64 %0, t; }"
        : "=r"(a) : "l"(p));
    return a;
}
#define SW128(o) ((o) ^ (((o) >> 3) & 0x70))

__device__ __forceinline__ void cp16(u32 dst, const void* src) {
    asm volatile("cp.async.cg.shared.global [%0], [%1], 16;" :: "r"(dst), "l"(src));
}
#define CP_COMMIT() asm volatile("cp.async.commit_group;" ::: "memory")

#define LDSM_X4(r0, r1, r2, r3, addr)                                        \
    asm volatile("ldmatrix.sync.aligned.m8n8.x4.shared.b16 {%0,%1,%2,%3}, [%4];" \
                 : "=r"(r0), "=r"(r1), "=r"(r2), "=r"(r3) : "r"(addr))

#define MMA_BF16(d, a, b0, b1)                                               \
    asm volatile("mma.sync.aligned.m16n8k16.row.col.f32.bf16.bf16.f32 "      \
                 "{%0,%1,%2,%3}, {%4,%5,%6,%7}, {%8,%9}, {%0,%1,%2,%3};"     \
                 : "+f"((d)[0]), "+f"((d)[1]), "+f"((d)[2]), "+f"((d)[3])    \
                 : "r"((a)[0]), "r"((a)[1]), "r"((a)[2]), "r"((a)[3]),       \
                   "r"(b0), "r"(b1))

// f32x2 helpers for the FFMA QKV kernel
__device__ __forceinline__ u64 pk2(float lo, float hi) {
    u64 r; asm("mov.b64 %0, {%1,%2};" : "=l"(r) : "f"(lo), "f"(hi)); return r;
}
__device__ __forceinline__ void fma2(u64& d, u64 a, u64 b) {
    asm("fma.rn.f32x2 %0, %1, %2, %0;" : "+l"(d) : "l"(a), "l"(b));
}
__device__ __forceinline__ void upk2(u64 v, float& lo, float& hi) {
    asm("mov.b64 {%0,%1}, %2;" : "=f"(lo), "=f"(hi) : "l"(v));
}

// ==================================================================
// Kernel 1: QKV projections (FFMA). Q/K written as bf16 hi/lo,
// V written fp32 (transposed+split later).
// ==================================================================
__global__ __launch_bounds__(256)
void qkv_proj_kernel(const float* __restrict__ x,
                     const float* __restrict__ Wq, const float* __restrict__ bq,
                     const float* __restrict__ Wk, const float* __restrict__ bk,
                     const float* __restrict__ Wv, const float* __restrict__ bv)
{
    __shared__ float Xs[16][132];
    __shared__ float Wsh[16][64];

    int t  = threadIdx.x;
    int m0 = blockIdx.x * 128;
    int nb = blockIdx.y;
    int which = nb >> 2;
    int n0 = (nb & 3) * 64;

    const float* W; const float* bias;
    if (which == 0)      { W = Wq; bias = bq; }
    else if (which == 1) { W = Wk; bias = bk; }
    else                 { W = Wv; bias = bv; }

    int tr = t >> 4, tc = t & 15;

    u64 acc[8][2];
    #pragma unroll
    for (int i = 0; i < 8; i++) { acc[i][0] = 0ull; acc[i][1] = 0ull; }

    for (int kc = 0; kc < Cn; kc += 16) {
        __syncthreads();
        for (int i = t; i < 512; i += 256) {
            int row = i >> 2, seg = i & 3;
            float4 v = *(const float4*)&x[(size_t)(m0 + row) * Cn + kc + seg * 4];
            Xs[seg*4+0][row] = v.x; Xs[seg*4+1][row] = v.y;
            Xs[seg*4+2][row] = v.z; Xs[seg*4+3][row] = v.w;
        }
        {
            int row = t >> 4, seg = t & 15;
            *(float4*)&Wsh[row][seg*4] =
                *(const float4*)&W[(size_t)(kc + row) * 256 + n0 + seg * 4];
        }
        __syncthreads();

        #pragma unroll
        for (int k = 0; k < 16; ++k) {
            float4 a0 = *(float4*)&Xs[k][tr*8];
            float4 a1 = *(float4*)&Xs[k][tr*8 + 4];
            float4 bb = *(float4*)&Wsh[k][tc*4];
            u64 b01 = pk2(bb.x, bb.y), b23 = pk2(bb.z, bb.w);
            float av[8] = {a0.x,a0.y,a0.z,a0.w,a1.x,a1.y,a1.z,a1.w};
            #pragma unroll
            for (int i = 0; i < 8; ++i) {
                u64 ad = pk2(av[i], av[i]);
                fma2(acc[i][0], ad, b01);
                fma2(acc[i][1], ad, b23);
            }
        }
    }

    float4 bb4 = *(const float4*)&bias[n0 + tc*4];
    #pragma unroll
    for (int i = 0; i < 8; ++i) {
        float v[4];
        upk2(acc[i][0], v[0], v[1]);
        upk2(acc[i][1], v[2], v[3]);
        v[0] += bb4.x; v[1] += bb4.y; v[2] += bb4.z; v[3] += bb4.w;
        size_t idx = (size_t)(m0 + tr*8 + i) * 256 + n0 + tc*4;
        if (which == 2) {
            float4 r; r.x = v[0]; r.y = v[1]; r.z = v[2]; r.w = v[3];
            *(float4*)&g_V[idx] = r;
        } else {
            union { __nv_bfloat16 h[4]; uint2 q; } H, L;
            #pragma unroll
            for (int j = 0; j < 4; ++j) {
                H.h[j] = __float2bfloat16(v[j]);
                L.h[j] = __float2bfloat16(v[j] - __bfloat162float(H.h[j]));
            }
            if (which == 0) {
                *(uint2*)&g_Qh[idx] = H.q;
                *(uint2*)&g_Ql[idx] = L.q;
            } else {
                *(uint2*)&g_Kh[idx] = H.q;
                *(uint2*)&g_Kl[idx] = L.q;
            }
        }
    }
}

// ==================================================================
// Kernel 2: transpose + split-convert V -> Vt[b][e][s]
// ==================================================================
__global__ __launch_bounds__(256)
void conv_v_kernel()
{
    __shared__ float tile[32][33];
    int b  = blockIdx.z;
    int s0 = blockIdx.x * 32, e0 = blockIdx.y * 32;
    int tx = threadIdx.x, ty = threadIdx.y;

    #pragma unroll
    for (int j = ty; j < 32; j += 8)
        tile[j][tx] = g_V[((size_t)(b * Sn + s0 + j)) * En + e0 + tx];
    __syncthreads();
    #pragma unroll
    for (int j = ty; j < 32; j += 8) {
        float v = tile[tx][j];   // = V[s0+tx][e0+j]
        __nv_bfloat16 hi = __float2bfloat16(v);
        __nv_bfloat16 lo = __float2bfloat16(v - __bfloat162float(hi));
        size_t o = ((size_t)(b * En + e0 + j)) * Sn + s0 + tx;
        g_Vth[o] = hi;
        g_Vtl[o] = lo;
    }
}

// ==================================================================
// mma.sync GEMM core: block tile 128(M) x 256(N), fp32 accum,
// D = (Ah+Al) @ (Bh+Bl)^T with 3 terms; K in chunks of 64.
// 8 warps: warp_m = wid&1 (2), warp_n = wid>>1 (4); warp tile 64x64.
// ==================================================================
#define OFF_AH 0
#define OFF_AL (16*1024)
#define OFF_BH (32*1024)
#define OFF_BL (64*1024)
#define CHUNK_BYTES (96*1024)
#define SMEM_GEMM (2*CHUNK_BYTES + 1024)

__device__ __forceinline__ void load_chunk(u32 buf,
    const __nv_bfloat16* Ah, const __nv_bfloat16* Al, int as,
    const __nv_bfloat16* Bh, const __nv_bfloat16* Bl, int bs,
    int c0, int t)
{
    #pragma unroll
    for (int j = 0; j < 4; ++j) {      // A_hi: 128 rows x 8 16B segs
        int idx = t + 256 * j; int row = idx >> 3, g = idx & 7;
        cp16(buf + OFF_AH + SW128(row*128 + g*16), Ah + (size_t)row*as + c0 + g*8);
    }
    #pragma unroll
    for (int j = 0; j < 4; ++j) {      // A_lo
        int idx = t + 256 * j; int row = idx >> 3, g = idx & 7;
        cp16(buf + OFF_AL + SW128(row*128 + g*16), Al + (size_t)row*as + c0 + g*8);
    }
    #pragma unroll
    for (int j = 0; j < 8; ++j) {      // B_hi: 256 rows x 8 segs
        int idx = t + 256 * j; int row = idx >> 3, g = idx & 7;
        cp16(buf + OFF_BH + SW128(row*128 + g*16), Bh + (size_t)row*bs + c0 + g*8);
    }
    #pragma unroll
    for (int j = 0; j < 8; ++j) {      // B_lo
        int idx = t + 256 * j; int row = idx >> 3, g = idx & 7;
        cp16(buf + OFF_BL + SW128(row*128 + g*16), Bl + (size_t)row*bs + c0 + g*8);
    }
    CP_COMMIT();
}

__device__ __forceinline__ void gemm_mma_loop(
    u32 base, float acc[4][8][4],
    const __nv_bfloat16* Ah, const __nv_bfloat16* Al, int as,
    const __nv_bfloat16* Bh, const __nv_bfloat16* Bl, int bs,
    int nchunk, int t)
{
    int wid = t >> 5, lane = t & 31;
    int warp_m = wid & 1, warp_n = wid >> 1;
    // ldmatrix per-lane source rows
    int a_row = warp_m*64 + (lane & 15);
    int a_ck  = (lane >> 4) & 1;
    int b_row = warp_n*64 + (lane & 7) + ((lane >> 4) << 3);
    int b_ck  = (lane >> 3) & 1;

    load_chunk(base, Ah, Al, as, Bh, Bl, bs, 0, t);

    for (int kc = 0; kc < nchunk; ++kc) {
        if (kc + 1 < nchunk) {
            load_chunk(base + ((kc+1)&1)*CHUNK_BYTES,
                       Ah, Al, as, Bh, Bl, bs, (kc+1)*64, t);
            asm volatile("cp.async.wait_group 1;" ::: "memory");
        } else {
            asm volatile("cp.async.wait_group 0;" ::: "memory");
        }
        __syncthreads();

        u32 buf = base + (kc & 1) * CHUNK_BYTES;
        #pragma unroll
        for (int ks = 0; ks < 4; ++ks) {
            u32 ah[4][4], al[4][4];
            #pragma unroll
            for (int mt = 0; mt < 4; ++mt) {
                int off = (a_row + mt*16)*128 + (2*ks + a_ck)*16;
                u32 sw = SW128(off);
                LDSM_X4(ah[mt][0], ah[mt][1], ah[mt][2], ah[mt][3],
                        buf + OFF_AH + sw);
                LDSM_X4(al[mt][0], al[mt][1], al[mt][2], al[mt][3],
                        buf + OFF_AL + sw);
            }
            #pragma unroll
            for (int np = 0; np < 4; ++np) {
                int off = (b_row + np*16)*128 + (2*ks + b_ck)*16;
                u32 sw = SW128(off);
                u32 bh[4], bl[4];
                LDSM_X4(bh[0], bh[1], bh[2], bh[3], buf + OFF_BH + sw);
                LDSM_X4(bl[0], bl[1], bl[2], bl[3], buf + OFF_BL + sw);
                #pragma unroll
                for (int mt = 0; mt < 4; ++mt) {
                    #pragma unroll
                    for (int j = 0; j < 2; ++j) {
                        MMA_BF16(acc[mt][np*2+j], ah[mt], bh[2*j], bh[2*j+1]);
                        MMA_BF16(acc[mt][np*2+j], ah[mt], bl[2*j], bl[2*j+1]);
                        MMA_BF16(acc[mt][np*2+j], al[mt], bh[2*j], bh[2*j+1]);
                    }
                }
            }
        }
        __syncthreads();
    }
}

// ==================================================================
// Kernel 3: scores S[b] = Q[b] @ K[b]^T  (fp32 to gmem)
// grid (32 mtiles, 16 ntiles, 4 batches), 256 threads
// ==================================================================
__global__ __launch_bounds__(256, 1)
void scores_kernel()
{
    extern __shared__ __align__(1024) char dsm[];
    u32 sb0  = smem_u32(dsm);
    u32 base = (sb0 + 1023) & ~1023u;
    int t = threadIdx.x, wid = t >> 5, lane = t & 31;
    int warp_m = wid & 1, warp_n = wid >> 1;

    int b = blockIdx.z, m0 = blockIdx.x * 128, n0 = blockIdx.y * 256;
    const __nv_bfloat16* Ah = g_Qh + ((size_t)(b * Sn + m0)) * Cn;
    const __nv_bfloat16* Al = g_Ql + ((size_t)(b * Sn + m0)) * Cn;
    const __nv_bfloat16* Bh = g_Kh + ((size_t)(b * Sn + n0)) * Cn;
    const __nv_bfloat16* Bl = g_Kl + ((size_t)(b * Sn + n0)) * Cn;

    float acc[4][8][4];
    #pragma unroll
    for (int i = 0; i < 4; ++i)
        #pragma unroll
        for (int j = 0; j < 8; ++j)
            #pragma unroll
            for (int k = 0; k < 4; ++k) acc[i][j][k] = 0.f;

    gemm_mma_loop(base, acc, Ah, Al, Cn, Bh, Bl, Cn, 4, t);

    float* Sg = g_S + ((size_t)(b * Sn + m0)) * Sn + n0;
    int rg = warp_m*64 + (lane >> 2);
    int cg = warp_n*64 + (lane & 3) * 2;
    #pragma unroll
    for (int mt = 0; mt < 4; ++mt) {
        #pragma unroll
        for (int nt = 0; nt < 8; ++nt) {
            int r = rg + mt*16, c = cg + nt*8;
            float2 lo; lo.x = acc[mt][nt][0]; lo.y = acc[mt][nt][1];
            float2 hi; hi.x = acc[mt][nt][2]; hi.y = acc[mt][nt][3];
            *(float2*)&Sg[(size_t)r * Sn + c]       = lo;
            *(float2*)&Sg[(size_t)(r + 8) * Sn + c] = hi;
        }
    }
}

// ==================================================================
// Kernel 4: row softmax over 4096 keys -> normalized P as bf16 hi/lo
// ==================================================================
__global__ __launch_bounds__(256)
void softmax_kernel()
{
    __shared__ float red[8];
    size_t row = blockIdx.x;
    const float* src = g_S + row * (size_t)Sn;
    int t = threadIdx.x, lane = t & 31, w = t >> 5;

    float vals[16];
    #pragma unroll
    for (int j = 0; j < 4; ++j) {
        float4 v = *(const float4*)&src[t*16 + j*4];
        vals[j*4+0] = v.x; vals[j*4+1] = v.y; vals[j*4+2] = v.z; vals[j*4+3] = v.w;
    }
    float m = vals[0];
    #pragma unroll
    for (int i = 1; i < 16; ++i) m = fmaxf(m, vals[i]);
    #pragma unroll
    for (int off = 16; off > 0; off >>= 1)
        m = fmaxf(m, __shfl_xor_sync(0xffffffffu, m, off));
    if (lane == 0) red[w] = m;
    __syncthreads();
    m = red[0];
    #pragma unroll
    for (int i = 1; i < 8; ++i) m = fmaxf(m, red[i]);
    __syncthreads();

    float s = 0.f;
    #pragma unroll
    for (int i = 0; i < 16; ++i) { vals[i] = __expf(vals[i] - m); s += vals[i]; }
    #pragma unroll
    for (int off = 16; off > 0; off >>= 1)
        s += __shfl_xor_sync(0xffffffffu, s, off);
    if (lane == 0) red[w] = s;
    __syncthreads();
    s = red[0];
    #pragma unroll
    for (int i = 1; i < 8; ++i) s += red[i];
    float inv = 1.0f / s;

    union { __nv_bfloat16 h[16]; uint4 q[2]; } H, L;
    #pragma unroll
    for (int i = 0; i < 16; ++i) {
        float p = vals[i] * inv;
        __nv_bfloat16 hi = __float2bfloat16(p);
        H.h[i] = hi;
        L.h[i] = __float2bfloat16(p - __bfloat162float(hi));
    }
    size_t o = row * (size_t)Sn + t * 16;
    *(uint4*)&g_Ph[o]     = H.q[0];
    *(uint4*)&g_Ph[o + 8] = H.q[1];
    *(uint4*)&g_Pl[o]     = L.q[0];
    *(uint4*)&g_Pl[o + 8] = L.q[1];
}

// ==================================================================
// Kernel 5: attended = P @ V, sigmoid, store. N tile = 256 = En.
// grid (32 mtiles, 1, 4 batches), 256 threads
// ==================================================================
__global__ __launch_bounds__(256, 1)
void pv_kernel(float* __restrict__ out)
{
    extern __shared__ __align__(1024) char dsm[];
    u32 sb0  = smem_u32(dsm);
    u32 base = (sb0 + 1023) & ~1023u;
    int t = threadIdx.x, wid = t >> 5, lane = t & 31;
    int warp_m = wid & 1, warp_n = wid >> 1;

    int b = blockIdx.z, m0 = blockIdx.x * 128;
    const __nv_bfloat16* Ah = g_Ph + ((size_t)b * Sn + m0) * Sn;
    const __nv_bfloat16* Al = g_Pl + ((size_t)b * Sn + m0) * Sn;
    const __nv_bfloat16* Bh = g_Vth + (size_t)b * En * Sn;   // rows = e
    const __nv_bfloat16* Bl = g_Vtl + (size_t)b * En * Sn;

    float acc[4][8][4];
    #pragma unroll
    for (int i = 0; i < 4; ++i)
        #pragma unroll
        for (int j = 0; j < 8; ++j)
            #pragma unroll
            for (int k = 0; k < 4; ++k) acc[i][j][k] = 0.f;

    gemm_mma_loop(base, acc, Ah, Al, Sn, Bh, Bl, Sn, Sn/64, t);

    float* Og = out + ((size_t)(b * Sn + m0)) * En;
    int rg = warp_m*64 + (lane >> 2);
    int cg = warp_n*64 + (lane & 3) * 2;
    #pragma unroll
    for (int mt = 0; mt < 4; ++mt) {
        #pragma unroll
        for (int nt = 0; nt < 8; ++nt) {
            int r = rg + mt*16, c = cg + nt*8;
            float2 lo, hi;
            lo.x = 1.0f / (1.0f + __expf(-acc[mt][nt][0]));
            lo.y = 1.0f / (1.0f + __expf(-acc[mt][nt][1]));
            hi.x = 1.0f / (1.0f + __expf(-acc[mt][nt][2]));
            hi.y = 1.0f / (1.0f + __expf(-acc[mt][nt][3]));
            *(float2*)&Og[(size_t)r * En + c]       = lo;
            *(float2*)&Og[(size_t)(r + 8) * En + c] = hi;
        }
    }
}

// ==================================================================
// Launch
// ==================================================================
extern "C" void kernel_launch(void* const* d_in, const int* in_sizes, int n_in,
                              void* d_out, int out_size)
{
    const float* x  = (const float*)d_in[0];
    const float* Wq = (const float*)d_in[1];
    const float* bq = (const float*)d_in[2];
    const float* Wk = (const float*)d_in[3];
    const float* bk = (const float*)d_in[4];
    const float* Wv = (const float*)d_in[5];
    const float* bv = (const float*)d_in[6];
    float* out = (float*)d_out;

    cudaFuncSetAttribute(scores_kernel,
        cudaFuncAttributeMaxDynamicSharedMemorySize, SMEM_GEMM);
    cudaFuncSetAttribute(pv_kernel,
        cudaFuncAttributeMaxDynamicSharedMemorySize, SMEM_GEMM);

    qkv_proj_kernel<<<dim3(128, 12), 256>>>(x, Wq, bq, Wk, bk, Wv, bv);
    conv_v_kernel<<<dim3(128, 8, 4), dim3(32, 8)>>>();
    scores_kernel<<<dim3(32, 16, 4), 256, SMEM_GEMM>>>();
    softmax_kernel<<<16384, 256>>>();
    pv_kernel<<<dim3(32, 1, 4), 256, SMEM_GEMM>>>(out);
}

// round 4
// speedup vs baseline: 4.0489x; 1.3818x over previous
#include <cuda_runtime.h>
#include <cuda_bf16.h>
#include <cuda_fp16.h>
#include <math.h>
#include <stdint.h>

#define Bn 4
#define Sn 4096
#define Cn 256
#define En 256

typedef unsigned int u32;
typedef unsigned long long u64;

// ------------------------------------------------------------------
// Static device scratch (no allocation allowed)
// ------------------------------------------------------------------
__device__ float g_V[Bn * Sn * En];
__device__ __nv_bfloat16 g_Qh[Bn * Sn * Cn];
__device__ __nv_bfloat16 g_Ql[Bn * Sn * Cn];
__device__ __nv_bfloat16 g_Kh[Bn * Sn * Cn];
__device__ __nv_bfloat16 g_Kl[Bn * Sn * Cn];
__device__ __half g_Vt[Bn * En * Sn];                 // V transposed fp16: [b][e][s]
__device__ float g_S[(size_t)Bn * Sn * Sn];           // 256 MB scores
__device__ __half g_P[(size_t)Bn * Sn * Sn];          // 128 MB normalized probs

// ------------------------------------------------------------------
// helpers
// ------------------------------------------------------------------
__device__ __forceinline__ u32 smem_u32(const void* p) {
    u32 a;
    asm("{ .reg .u64 t; cvta.to.shared.u64 t, %1; cvt.u32.u64 %0, t; }"
        : "=r"(a) : "l"(p));
    return a;
}
#define SW128(o) ((o) ^ (((o) >> 3) & 0x70))

__device__ __forceinline__ void cp16(u32 dst, const void* src) {
    asm volatile("cp.async.cg.shared.global [%0], [%1], 16;" :: "r"(dst), "l"(src));
}
#define CP_COMMIT() asm volatile("cp.async.commit_group;" ::: "memory")

#define LDSM_X4(r0, r1, r2, r3, addr)                                        \
    asm volatile("ldmatrix.sync.aligned.m8n8.x4.shared.b16 {%0,%1,%2,%3}, [%4];" \
                 : "=r"(r0), "=r"(r1), "=r"(r2), "=r"(r3) : "r"(addr))

#define MMA_BF16(d, a, b0, b1)                                               \
    asm volatile("mma.sync.aligned.m16n8k16.row.col.f32.bf16.bf16.f32 "      \
                 "{%0,%1,%2,%3}, {%4,%5,%6,%7}, {%8,%9}, {%0,%1,%2,%3};"     \
                 : "+f"((d)[0]), "+f"((d)[1]), "+f"((d)[2]), "+f"((d)[3])    \
                 : "r"((a)[0]), "r"((a)[1]), "r"((a)[2]), "r"((a)[3]),       \
                   "r"(b0), "r"(b1))

#define MMA_F16(d, a, b0, b1)                                                \
    asm volatile("mma.sync.aligned.m16n8k16.row.col.f32.f16.f16.f32 "        \
                 "{%0,%1,%2,%3}, {%4,%5,%6,%7}, {%8,%9}, {%0,%1,%2,%3};"     \
                 : "+f"((d)[0]), "+f"((d)[1]), "+f"((d)[2]), "+f"((d)[3])    \
                 : "r"((a)[0]), "r"((a)[1]), "r"((a)[2]), "r"((a)[3]),       \
                   "r"(b0), "r"(b1))

// f32x2 helpers for the FFMA QKV kernel
__device__ __forceinline__ u64 pk2(float lo, float hi) {
    u64 r; asm("mov.b64 %0, {%1,%2};" : "=l"(r) : "f"(lo), "f"(hi)); return r;
}
__device__ __forceinline__ void fma2(u64& d, u64 a, u64 b) {
    asm("fma.rn.f32x2 %0, %1, %2, %0;" : "+l"(d) : "l"(a), "l"(b));
}
__device__ __forceinline__ void upk2(u64 v, float& lo, float& hi) {
    asm("mov.b64 {%0,%1}, %2;" : "=f"(lo), "=f"(hi) : "l"(v));
}

// ==================================================================
// Kernel 1: QKV projections (FFMA). Q/K written as bf16 hi/lo,
// V written fp32 (transposed+converted later).
// ==================================================================
__global__ __launch_bounds__(256)
void qkv_proj_kernel(const float* __restrict__ x,
                     const float* __restrict__ Wq, const float* __restrict__ bq,
                     const float* __restrict__ Wk, const float* __restrict__ bk,
                     const float* __restrict__ Wv, const float* __restrict__ bv)
{
    __shared__ float Xs[16][132];
    __shared__ float Wsh[16][64];

    int t  = threadIdx.x;
    int m0 = blockIdx.x * 128;
    int nb = blockIdx.y;
    int which = nb >> 2;
    int n0 = (nb & 3) * 64;

    const float* W; const float* bias;
    if (which == 0)      { W = Wq; bias = bq; }
    else if (which == 1) { W = Wk; bias = bk; }
    else                 { W = Wv; bias = bv; }

    int tr = t >> 4, tc = t & 15;

    u64 acc[8][2];
    #pragma unroll
    for (int i = 0; i < 8; i++) { acc[i][0] = 0ull; acc[i][1] = 0ull; }

    for (int kc = 0; kc < Cn; kc += 16) {
        __syncthreads();
        for (int i = t; i < 512; i += 256) {
            int row = i >> 2, seg = i & 3;
            float4 v = *(const float4*)&x[(size_t)(m0 + row) * Cn + kc + seg * 4];
            Xs[seg*4+0][row] = v.x; Xs[seg*4+1][row] = v.y;
            Xs[seg*4+2][row] = v.z; Xs[seg*4+3][row] = v.w;
        }
        {
            int row = t >> 4, seg = t & 15;
            *(float4*)&Wsh[row][seg*4] =
                *(const float4*)&W[(size_t)(kc + row) * 256 + n0 + seg * 4];
        }
        __syncthreads();

        #pragma unroll
        for (int k = 0; k < 16; ++k) {
            float4 a0 = *(float4*)&Xs[k][tr*8];
            float4 a1 = *(float4*)&Xs[k][tr*8 + 4];
            float4 bb = *(float4*)&Wsh[k][tc*4];
            u64 b01 = pk2(bb.x, bb.y), b23 = pk2(bb.z, bb.w);
            float av[8] = {a0.x,a0.y,a0.z,a0.w,a1.x,a1.y,a1.z,a1.w};
            #pragma unroll
            for (int i = 0; i < 8; ++i) {
                u64 ad = pk2(av[i], av[i]);
                fma2(acc[i][0], ad, b01);
                fma2(acc[i][1], ad, b23);
            }
        }
    }

    float4 bb4 = *(const float4*)&bias[n0 + tc*4];
    #pragma unroll
    for (int i = 0; i < 8; ++i) {
        float v[4];
        upk2(acc[i][0], v[0], v[1]);
        upk2(acc[i][1], v[2], v[3]);
        v[0] += bb4.x; v[1] += bb4.y; v[2] += bb4.z; v[3] += bb4.w;
        size_t idx = (size_t)(m0 + tr*8 + i) * 256 + n0 + tc*4;
        if (which == 2) {
            float4 r; r.x = v[0]; r.y = v[1]; r.z = v[2]; r.w = v[3];
            *(float4*)&g_V[idx] = r;
        } else {
            union { __nv_bfloat16 h[4]; uint2 q; } H, L;
            #pragma unroll
            for (int j = 0; j < 4; ++j) {
                H.h[j] = __float2bfloat16(v[j]);
                L.h[j] = __float2bfloat16(v[j] - __bfloat162float(H.h[j]));
            }
            if (which == 0) {
                *(uint2*)&g_Qh[idx] = H.q;
                *(uint2*)&g_Ql[idx] = L.q;
            } else {
                *(uint2*)&g_Kh[idx] = H.q;
                *(uint2*)&g_Kl[idx] = L.q;
            }
        }
    }
}

// ==================================================================
// Kernel 2: transpose + convert V -> Vt[b][e][s] fp16
// ==================================================================
__global__ __launch_bounds__(256)
void conv_v_kernel()
{
    __shared__ float tile[32][33];
    int b  = blockIdx.z;
    int s0 = blockIdx.x * 32, e0 = blockIdx.y * 32;
    int tx = threadIdx.x, ty = threadIdx.y;

    #pragma unroll
    for (int j = ty; j < 32; j += 8)
        tile[j][tx] = g_V[((size_t)(b * Sn + s0 + j)) * En + e0 + tx];
    __syncthreads();
    #pragma unroll
    for (int j = ty; j < 32; j += 8) {
        float v = tile[tx][j];   // = V[s0+tx][e0+j]
        size_t o = ((size_t)(b * En + e0 + j)) * Sn + s0 + tx;
        g_Vt[o] = __float2half_rn(v);
    }
}

// ==================================================================
// Scores GEMM core (bf16 split, 3 terms): tile 128(M) x 256(N),
// K in double-buffered chunks of 64.
// ==================================================================
#define OFF_AH 0
#define OFF_AL (16*1024)
#define OFF_BH (32*1024)
#define OFF_BL (64*1024)
#define CHUNK_BYTES (96*1024)
#define SMEM_GEMM (2*CHUNK_BYTES + 1024)

__device__ __forceinline__ void load_chunk(u32 buf,
    const __nv_bfloat16* Ah, const __nv_bfloat16* Al,
    const __nv_bfloat16* Bh, const __nv_bfloat16* Bl,
    int c0, int t)
{
    #pragma unroll
    for (int j = 0; j < 4; ++j) {
        int idx = t + 256 * j; int row = idx >> 3, g = idx & 7;
        cp16(buf + OFF_AH + SW128(row*128 + g*16), Ah + (size_t)row*Cn + c0 + g*8);
    }
    #pragma unroll
    for (int j = 0; j < 4; ++j) {
        int idx = t + 256 * j; int row = idx >> 3, g = idx & 7;
        cp16(buf + OFF_AL + SW128(row*128 + g*16), Al + (size_t)row*Cn + c0 + g*8);
    }
    #pragma unroll
    for (int j = 0; j < 8; ++j) {
        int idx = t + 256 * j; int row = idx >> 3, g = idx & 7;
        cp16(buf + OFF_BH + SW128(row*128 + g*16), Bh + (size_t)row*Cn + c0 + g*8);
    }
    #pragma unroll
    for (int j = 0; j < 8; ++j) {
        int idx = t + 256 * j; int row = idx >> 3, g = idx & 7;
        cp16(buf + OFF_BL + SW128(row*128 + g*16), Bl + (size_t)row*Cn + c0 + g*8);
    }
    CP_COMMIT();
}

// ==================================================================
// Kernel 3: scores S[b] = Q[b] @ K[b]^T (fp32, coalesced via smem stage)
// ==================================================================
__global__ __launch_bounds__(256, 1)
void scores_kernel()
{
    extern __shared__ __align__(1024) char dsm[];
    u32 sb0  = smem_u32(dsm);
    u32 base = (sb0 + 1023) & ~1023u;
    char* alig = dsm + (base - sb0);
    int t = threadIdx.x, wid = t >> 5, lane = t & 31;
    int warp_m = wid & 1, warp_n = wid >> 1;

    int b = blockIdx.z, m0 = blockIdx.x * 128, n0 = blockIdx.y * 256;
    const __nv_bfloat16* Ah = g_Qh + ((size_t)(b * Sn + m0)) * Cn;
    const __nv_bfloat16* Al = g_Ql + ((size_t)(b * Sn + m0)) * Cn;
    const __nv_bfloat16* Bh = g_Kh + ((size_t)(b * Sn + n0)) * Cn;
    const __nv_bfloat16* Bl = g_Kl + ((size_t)(b * Sn + n0)) * Cn;

    float acc[4][8][4];
    #pragma unroll
    for (int i = 0; i < 4; ++i)
        #pragma unroll
        for (int j = 0; j < 8; ++j)
            #pragma unroll
            for (int k = 0; k < 4; ++k) acc[i][j][k] = 0.f;

    int a_row = warp_m*64 + (lane & 15);
    int a_ck  = (lane >> 4) & 1;
    int b_row = warp_n*64 + (lane & 7) + ((lane >> 4) << 3);
    int b_ck  = (lane >> 3) & 1;

    load_chunk(base, Ah, Al, Bh, Bl, 0, t);

    for (int kc = 0; kc < 4; ++kc) {
        if (kc + 1 < 4) {
            load_chunk(base + ((kc+1)&1)*CHUNK_BYTES, Ah, Al, Bh, Bl, (kc+1)*64, t);
            asm volatile("cp.async.wait_group 1;" ::: "memory");
        } else {
            asm volatile("cp.async.wait_group 0;" ::: "memory");
        }
        __syncthreads();

        u32 buf = base + (kc & 1) * CHUNK_BYTES;
        #pragma unroll
        for (int ks = 0; ks < 4; ++ks) {
            u32 ah[4][4], al[4][4];
            #pragma unroll
            for (int mt = 0; mt < 4; ++mt) {
                int off = (a_row + mt*16)*128 + (2*ks + a_ck)*16;
                u32 sw = SW128(off);
                LDSM_X4(ah[mt][0], ah[mt][1], ah[mt][2], ah[mt][3], buf + OFF_AH + sw);
                LDSM_X4(al[mt][0], al[mt][1], al[mt][2], al[mt][3], buf + OFF_AL + sw);
            }
            #pragma unroll
            for (int np = 0; np < 4; ++np) {
                int off = (b_row + np*16)*128 + (2*ks + b_ck)*16;
                u32 sw = SW128(off);
                u32 bh[4], bl[4];
                LDSM_X4(bh[0], bh[1], bh[2], bh[3], buf + OFF_BH + sw);
                LDSM_X4(bl[0], bl[1], bl[2], bl[3], buf + OFF_BL + sw);
                #pragma unroll
                for (int mt = 0; mt < 4; ++mt) {
                    #pragma unroll
                    for (int j = 0; j < 2; ++j) {
                        MMA_BF16(acc[mt][np*2+j], ah[mt], bh[2*j], bh[2*j+1]);
                        MMA_BF16(acc[mt][np*2+j], ah[mt], bl[2*j], bl[2*j+1]);
                        MMA_BF16(acc[mt][np*2+j], al[mt], bh[2*j], bh[2*j+1]);
                    }
                }
            }
        }
        __syncthreads();
    }

    // epilogue: stage in smem (stride 260 to dodge conflicts), coalesced write
    float* stage = (float*)alig;
    int rg = warp_m*64 + (lane >> 2);
    int cg = warp_n*64 + (lane & 3) * 2;
    #pragma unroll
    for (int mt = 0; mt < 4; ++mt) {
        #pragma unroll
        for (int nt = 0; nt < 8; ++nt) {
            int r = rg + mt*16, c = cg + nt*8;
            float2 lo; lo.x = acc[mt][nt][0]; lo.y = acc[mt][nt][1];
            float2 hi; hi.x = acc[mt][nt][2]; hi.y = acc[mt][nt][3];
            *(float2*)&stage[r*260 + c]       = lo;
            *(float2*)&stage[(r+8)*260 + c]   = hi;
        }
    }
    __syncthreads();
    float* Sg = g_S + ((size_t)(b * Sn + m0)) * Sn + n0;
    #pragma unroll
    for (int i = t; i < 128*64; i += 256) {
        int row = i >> 6, s4 = i & 63;
        float4 v = *(float4*)&stage[row*260 + s4*4];
        *(float4*)&Sg[(size_t)row * Sn + s4*4] = v;
    }
}

// ==================================================================
// Kernel 4: row softmax over 4096 keys -> normalized P as fp16
// ==================================================================
__global__ __launch_bounds__(256)
void softmax_kernel()
{
    __shared__ float red[8];
    size_t row = blockIdx.x;
    const float* src = g_S + row * (size_t)Sn;
    int t = threadIdx.x, lane = t & 31, w = t >> 5;

    float vals[16];
    #pragma unroll
    for (int j = 0; j < 4; ++j) {
        float4 v = *(const float4*)&src[t*16 + j*4];
        vals[j*4+0] = v.x; vals[j*4+1] = v.y; vals[j*4+2] = v.z; vals[j*4+3] = v.w;
    }
    float m = vals[0];
    #pragma unroll
    for (int i = 1; i < 16; ++i) m = fmaxf(m, vals[i]);
    #pragma unroll
    for (int off = 16; off > 0; off >>= 1)
        m = fmaxf(m, __shfl_xor_sync(0xffffffffu, m, off));
    if (lane == 0) red[w] = m;
    __syncthreads();
    m = red[0];
    #pragma unroll
    for (int i = 1; i < 8; ++i) m = fmaxf(m, red[i]);
    __syncthreads();

    float s = 0.f;
    #pragma unroll
    for (int i = 0; i < 16; ++i) { vals[i] = __expf(vals[i] - m); s += vals[i]; }
    #pragma unroll
    for (int off = 16; off > 0; off >>= 1)
        s += __shfl_xor_sync(0xffffffffu, s, off);
    if (lane == 0) red[w] = s;
    __syncthreads();
    s = red[0];
    #pragma unroll
    for (int i = 1; i < 8; ++i) s += red[i];
    float inv = 1.0f / s;

    union { __half h[16]; uint4 q[2]; } H;
    #pragma unroll
    for (int i = 0; i < 16; ++i)
        H.h[i] = __float2half_rn(vals[i] * inv);
    size_t o = row * (size_t)Sn + t * 16;
    *(uint4*)&g_P[o]     = H.q[0];
    *(uint4*)&g_P[o + 8] = H.q[1];
}

// ==================================================================
// Kernel 5: attended = P @ V (single-term fp16), sigmoid, store.
// Block tile 128(M) x 256(N=En), chunks of 64 keys, double-buffered.
// ==================================================================
#define PV_OFF_A 0
#define PV_OFF_B (16*1024)
#define PV_CHUNK (48*1024)
#define SMEM_PV  (2*PV_CHUNK + 1024)

__device__ __forceinline__ void load_pv(u32 buf,
    const __half* A, const __half* B, int c0, int t)
{
    #pragma unroll
    for (int j = 0; j < 4; ++j) {      // P: 128 rows x 8 segs
        int idx = t + 256 * j; int row = idx >> 3, g = idx & 7;
        cp16(buf + PV_OFF_A + SW128(row*128 + g*16), A + (size_t)row*Sn + c0 + g*8);
    }
    #pragma unroll
    for (int j = 0; j < 8; ++j) {      // Vt: 256 rows x 8 segs
        int idx = t + 256 * j; int row = idx >> 3, g = idx & 7;
        cp16(buf + PV_OFF_B + SW128(row*128 + g*16), B + (size_t)row*Sn + c0 + g*8);
    }
    CP_COMMIT();
}

__global__ __launch_bounds__(256, 1)
void pv_kernel(float* __restrict__ out)
{
    extern __shared__ __align__(1024) char dsm[];
    u32 sb0  = smem_u32(dsm);
    u32 base = (sb0 + 1023) & ~1023u;
    int t = threadIdx.x, wid = t >> 5, lane = t & 31;
    int warp_m = wid & 1, warp_n = wid >> 1;

    int b = blockIdx.z, m0 = blockIdx.x * 128;
    const __half* A = g_P + ((size_t)b * Sn + m0) * Sn;
    const __half* B = g_Vt + (size_t)b * En * Sn;

    float acc[4][8][4];
    #pragma unroll
    for (int i = 0; i < 4; ++i)
        #pragma unroll
        for (int j = 0; j < 8; ++j)
            #pragma unroll
            for (int k = 0; k < 4; ++k) acc[i][j][k] = 0.f;

    int a_row = warp_m*64 + (lane & 15);
    int a_ck  = (lane >> 4) & 1;
    int b_row = warp_n*64 + (lane & 7) + ((lane >> 4) << 3);
    int b_ck  = (lane >> 3) & 1;

    const int NCHUNK = Sn / 64;
    load_pv(base, A, B, 0, t);

    for (int kc = 0; kc < NCHUNK; ++kc) {
        if (kc + 1 < NCHUNK) {
            load_pv(base + ((kc+1)&1)*PV_CHUNK, A, B, (kc+1)*64, t);
            asm volatile("cp.async.wait_group 1;" ::: "memory");
        } else {
            asm volatile("cp.async.wait_group 0;" ::: "memory");
        }
        __syncthreads();

        u32 buf = base + (kc & 1) * PV_CHUNK;
        #pragma unroll
        for (int ks = 0; ks < 4; ++ks) {
            u32 af[4][4];
            #pragma unroll
            for (int mt = 0; mt < 4; ++mt) {
                int off = (a_row + mt*16)*128 + (2*ks + a_ck)*16;
                LDSM_X4(af[mt][0], af[mt][1], af[mt][2], af[mt][3],
                        buf + PV_OFF_A + SW128(off));
            }
            #pragma unroll
            for (int np = 0; np < 4; ++np) {
                int off = (b_row + np*16)*128 + (2*ks + b_ck)*16;
                u32 bf[4];
                LDSM_X4(bf[0], bf[1], bf[2], bf[3], buf + PV_OFF_B + SW128(off));
                #pragma unroll
                for (int mt = 0; mt < 4; ++mt) {
                    #pragma unroll
                    for (int j = 0; j < 2; ++j)
                        MMA_F16(acc[mt][np*2+j], af[mt], bf[2*j], bf[2*j+1]);
                }
            }
        }
        __syncthreads();
    }

    float* Og = out + ((size_t)(b * Sn + m0)) * En;
    int rg = warp_m*64 + (lane >> 2);
    int cg = warp_n*64 + (lane & 3) * 2;
    #pragma unroll
    for (int mt = 0; mt < 4; ++mt) {
        #pragma unroll
        for (int nt = 0; nt < 8; ++nt) {
            int r = rg + mt*16, c = cg + nt*8;
            float2 lo, hi;
            lo.x = 1.0f / (1.0f + __expf(-acc[mt][nt][0]));
            lo.y = 1.0f / (1.0f + __expf(-acc[mt][nt][1]));
            hi.x = 1.0f / (1.0f + __expf(-acc[mt][nt][2]));
            hi.y = 1.0f / (1.0f + __expf(-acc[mt][nt][3]));
            *(float2*)&Og[(size_t)r * En + c]       = lo;
            *(float2*)&Og[(size_t)(r + 8) * En + c] = hi;
        }
    }
}

// ==================================================================
// Launch
// ==================================================================
extern "C" void kernel_launch(void* const* d_in, const int* in_sizes, int n_in,
                              void* d_out, int out_size)
{
    const float* x  = (const float*)d_in[0];
    const float* Wq = (const float*)d_in[1];
    const float* bq = (const float*)d_in[2];
    const float* Wk = (const float*)d_in[3];
    const float* bk = (const float*)d_in[4];
    const float* Wv = (const float*)d_in[5];
    const float* bv = (const float*)d_in[6];
    float* out = (float*)d_out;

    cudaFuncSetAttribute(scores_kernel,
        cudaFuncAttributeMaxDynamicSharedMemorySize, SMEM_GEMM);
    cudaFuncSetAttribute(pv_kernel,
        cudaFuncAttributeMaxDynamicSharedMemorySize, SMEM_PV);

    qkv_proj_kernel<<<dim3(128, 12), 256>>>(x, Wq, bq, Wk, bk, Wv, bv);
    conv_v_kernel<<<dim3(128, 8, 4), dim3(32, 8)>>>();
    scores_kernel<<<dim3(32, 16, 4), 256, SMEM_GEMM>>>();
    softmax_kernel<<<16384, 256>>>();
    pv_kernel<<<dim3(32, 1, 4), 256, SMEM_PV>>>(out);
}